// round 1
// baseline (speedup 1.0000x reference)
#include <cuda_runtime.h>
#include <cstdint>

// Problem constants (fixed by the dataset)
#define B_    8
#define V_    12288
#define E_    98304
#define FIN_  256
#define FOUT_ 256
#define KCH_  4
#define BF_   (B_*FIN_)    // 2048 floats per node row (node-major layout)
#define ROWS_ (B_*V_)      // 98304 output rows

// ---------------- scratch (device globals: no runtime allocation) ----------
__device__ float g_T1[(size_t)V_*BF_];   // T1 = L x          [V][B*Fin]
__device__ float g_T2[(size_t)V_*BF_];   // T2 = 2 L T1 - T0
__device__ float g_T3[(size_t)V_*BF_];   // T3 = 2 L T2 - T1
__device__ int   g_rowptr[V_+1];
__device__ int   g_cursor[V_];
__device__ int   g_cnt[V_];
__device__ int   g_col[E_];              // src indices sorted by dst
__device__ float g_w[E_];                // weights sorted by dst
__device__ float g_sum[FOUT_], g_sq[FOUT_];
__device__ float g_scale[FOUT_], g_shift[FOUT_];

// ---------------- CSR build -------------------------------------------------
__global__ void k_zero() {
    int i = blockIdx.x*blockDim.x + threadIdx.x;
    if (i < V_) g_cnt[i] = 0;
    if (i < FOUT_) { g_sum[i] = 0.f; g_sq[i] = 0.f; }
}

__global__ void k_hist(const int* __restrict__ dst) {
    int e = blockIdx.x*blockDim.x + threadIdx.x;
    if (e < E_) atomicAdd(&g_cnt[dst[e]], 1);
}

// exclusive scan over V_=12288 counts; 1 block of 1024 threads, 12 counts each
__global__ void k_scan() {
    __shared__ int sh[1024];
    int t = threadIdx.x;
    int base = t*12;
    int loc[12];
    int s = 0;
    #pragma unroll
    for (int i = 0; i < 12; ++i) { loc[i] = s; s += g_cnt[base+i]; }
    sh[t] = s;
    __syncthreads();
    for (int off = 1; off < 1024; off <<= 1) {
        int v = 0;
        if (t >= off) v = sh[t-off];
        __syncthreads();
        if (t >= off) sh[t] += v;
        __syncthreads();
    }
    int pre = (t == 0) ? 0 : sh[t-1];
    #pragma unroll
    for (int i = 0; i < 12; ++i) {
        int p = pre + loc[i];
        g_rowptr[base+i] = p;
        g_cursor[base+i] = p;
    }
    if (t == 1023) g_rowptr[V_] = sh[1023];
}

__global__ void k_scatter(const int* __restrict__ src, const int* __restrict__ dst,
                          const float* __restrict__ ew) {
    int e = blockIdx.x*blockDim.x + threadIdx.x;
    if (e < E_) {
        int d = dst[e];
        int p = atomicAdd(&g_cursor[d], 1);
        g_col[p] = src[e];
        g_w[p]   = ew[e];
    }
}

// ---------------- SpMM: Chebyshev recursion --------------------------------
// stage 1: T1 = L x            (x in [B][V][Fin] layout)
// stage 2: T2 = 2 L T1 - x
// stage 3: T3 = 2 L T2 - T1
__global__ __launch_bounds__(256) void k_spmm(const float* __restrict__ x, int stage) {
    const float* y;  const float* p2 = nullptr;  float* o;
    bool y_is_x = false; int p2m = 0;
    if (stage == 1)      { y = x;    y_is_x = true;      o = g_T1; }
    else if (stage == 2) { y = g_T1; p2 = x;  p2m = 1;   o = g_T2; }
    else                 { y = g_T2; p2 = g_T1; p2m = 2; o = g_T3; }

    int v  = blockIdx.x >> 1;
    int j0 = ((blockIdx.x & 1) << 10) | (threadIdx.x << 2);   // 0..2047
    int r0 = g_rowptr[v], r1 = g_rowptr[v+1];

    int  bb = j0 >> 8;
    int  f  = j0 & 255;
    long xoff = (long)bb * V_ * FIN_ + f;   // x[(b*V + s)*Fin + f]

    float ax = 0.f, ay = 0.f, az = 0.f, aw = 0.f;
    for (int e = r0; e < r1; ++e) {
        int   s  = __ldg(&g_col[e]);
        float we = __ldg(&g_w[e]);
        const float* yp = y_is_x ? (y + xoff + (long)s*FIN_)
                                 : (y + (long)s*BF_ + j0);
        float4 t = *(const float4*)yp;
        ax = fmaf(we, t.x, ax);
        ay = fmaf(we, t.y, ay);
        az = fmaf(we, t.z, az);
        aw = fmaf(we, t.w, aw);
    }
    if (p2m) {
        const float* pp = (p2m == 1) ? (p2 + xoff + (long)v*FIN_)
                                     : (p2 + (long)v*BF_ + j0);
        float4 t = *(const float4*)pp;
        ax = 2.f*ax - t.x;
        ay = 2.f*ay - t.y;
        az = 2.f*az - t.z;
        aw = 2.f*aw - t.w;
    }
    *(float4*)(o + (long)v*BF_ + j0) = make_float4(ax, ay, az, aw);
}

// ---------------- TF32 tensor-core GEMM -------------------------------------
// out[b,v,o] = sum_p sum_i A_p(v,b,i) * W[p,i,o]
// A_0 = x (layout [B][V][Fin]); A_1..3 = g_T1..3 (layout [V][B*Fin])
// Bias omitted: it cancels exactly through BatchNorm mean subtraction.
#define BM 128
#define BN 128
#define BK 32

__device__ __forceinline__ uint32_t f2tf(float f) {
    uint32_t u;
    asm("cvt.rna.tf32.f32 %0, %1;" : "=r"(u) : "f"(f));
    return u;
}

__global__ __launch_bounds__(256) void k_gemm(const float* __restrict__ x,
                                              const float* __restrict__ w,
                                              float* __restrict__ out) {
    __shared__ uint32_t As[BK][BM+4];   // k-major, padded stride 132
    __shared__ uint32_t Bs[BK][BN+4];

    const int b      = blockIdx.z;
    const int vbase  = blockIdx.x * BM;
    const int nbase0 = blockIdx.y * BN;
    const int tid  = threadIdx.x;
    const int lane = tid & 31, warp = tid >> 5;
    const int wm = warp & 3, wn = warp >> 2;       // 4 warps along M, 2 along N
    const int g = lane >> 2, tg = lane & 3;

    float acc[2][8][4];
    #pragma unroll
    for (int i = 0; i < 2; ++i)
        #pragma unroll
        for (int j = 0; j < 8; ++j)
            #pragma unroll
            for (int c = 0; c < 4; ++c) acc[i][j][c] = 0.f;

    const int a_c  = tid & 7;    // which k-quad (4 floats) in A tile
    const int a_m0 = tid >> 3;   // row 0..31 (x4)
    const int b_n4 = tid & 31;   // float4 column in B tile
    const int b_k0 = tid >> 5;   // k row 0..7 (x4)

    #pragma unroll 1
    for (int p = 0; p < KCH_; ++p) {
        const float* abase;
        long astride;
        if (p == 0)      { abase = x    + (long)b*V_*FIN_; astride = FIN_; }
        else if (p == 1) { abase = g_T1 + (long)b*FIN_;    astride = BF_;  }
        else if (p == 2) { abase = g_T2 + (long)b*FIN_;    astride = BF_;  }
        else             { abase = g_T3 + (long)b*FIN_;    astride = BF_;  }
        const float* wp = w + (long)p*FIN_*FOUT_ + nbase0;

        #pragma unroll 1
        for (int kb = 0; kb < FIN_; kb += BK) {
            __syncthreads();   // protect smem from previous stage's consumers
            // A tile: [BM rows][BK k], stored transposed k-major
            #pragma unroll
            for (int r = 0; r < 4; ++r) {
                int m = a_m0 + r*32;
                const float* src = abase + (long)(vbase+m)*astride + kb + a_c*4;
                float4 t = *(const float4*)src;
                As[a_c*4+0][m] = f2tf(t.x);
                As[a_c*4+1][m] = f2tf(t.y);
                As[a_c*4+2][m] = f2tf(t.z);
                As[a_c*4+3][m] = f2tf(t.w);
            }
            // B tile: [BK k][BN n], row-major
            #pragma unroll
            for (int r = 0; r < 4; ++r) {
                int kk = b_k0 + r*8;
                const float* src = wp + (long)(kb+kk)*FOUT_ + b_n4*4;
                float4 t = *(const float4*)src;
                uint32_t* d = &Bs[kk][b_n4*4];
                d[0] = f2tf(t.x); d[1] = f2tf(t.y);
                d[2] = f2tf(t.z); d[3] = f2tf(t.w);
            }
            __syncthreads();

            #pragma unroll
            for (int kk = 0; kk < BK; kk += 8) {
                uint32_t a[2][4];
                #pragma unroll
                for (int mt = 0; mt < 2; ++mt) {
                    int mb = wm*32 + mt*16;
                    a[mt][0] = As[kk+tg  ][mb+g  ];
                    a[mt][1] = As[kk+tg  ][mb+g+8];
                    a[mt][2] = As[kk+tg+4][mb+g  ];
                    a[mt][3] = As[kk+tg+4][mb+g+8];
                }
                #pragma unroll
                for (int nt = 0; nt < 8; ++nt) {
                    int nb = wn*64 + nt*8;
                    uint32_t b0 = Bs[kk+tg  ][nb+g];
                    uint32_t b1 = Bs[kk+tg+4][nb+g];
                    #pragma unroll
                    for (int mt = 0; mt < 2; ++mt) {
                        asm volatile(
                            "mma.sync.aligned.m16n8k8.row.col.f32.tf32.tf32.f32 "
                            "{%0,%1,%2,%3}, {%4,%5,%6,%7}, {%8,%9}, {%0,%1,%2,%3};\n"
                            : "+f"(acc[mt][nt][0]), "+f"(acc[mt][nt][1]),
                              "+f"(acc[mt][nt][2]), "+f"(acc[mt][nt][3])
                            : "r"(a[mt][0]), "r"(a[mt][1]),
                              "r"(a[mt][2]), "r"(a[mt][3]),
                              "r"(b0), "r"(b1));
                    }
                }
            }
        }
    }

    // epilogue: raw (pre-BN) result into d_out
    #pragma unroll
    for (int mt = 0; mt < 2; ++mt) {
        int row0 = vbase + wm*32 + mt*16 + g;
        #pragma unroll
        for (int nt = 0; nt < 8; ++nt) {
            int col = nbase0 + wn*64 + nt*8 + tg*2;
            float2* p0 = (float2*)&out[((long)b*V_ + row0    )*FOUT_ + col];
            float2* p1 = (float2*)&out[((long)b*V_ + row0 + 8)*FOUT_ + col];
            *p0 = make_float2(acc[mt][nt][0], acc[mt][nt][1]);
            *p1 = make_float2(acc[mt][nt][2], acc[mt][nt][3]);
        }
    }
}

// ---------------- BatchNorm (training stats) + ReLU -------------------------
__global__ __launch_bounds__(256) void k_bnstats(const float* __restrict__ out) {
    int o = threadIdx.x;
    float s = 0.f, q = 0.f;
    for (int r = blockIdx.x; r < ROWS_; r += gridDim.x) {
        float v = out[(long)r*FOUT_ + o];
        s += v;
        q = fmaf(v, v, q);
    }
    atomicAdd(&g_sum[o], s);
    atomicAdd(&g_sq[o],  q);
}

__global__ void k_bnfinal(const float* __restrict__ gamma,
                          const float* __restrict__ beta) {
    int o = threadIdx.x;
    const float n = (float)ROWS_;
    float mean = g_sum[o] / n;
    float var  = g_sq[o] / n - mean*mean;      // biased variance (torch-style)
    float sc   = gamma[o] * rsqrtf(var + 1e-5f);
    g_scale[o] = sc;
    g_shift[o] = beta[o] - mean*sc;
}

__global__ __launch_bounds__(256) void k_bnapply(float* __restrict__ out) {
    long i = ((long)blockIdx.x*blockDim.x + threadIdx.x) * 4;
    float4 v = *(float4*)(out + i);
    int o = (int)(i & 255);
    v.x = fmaxf(fmaf(v.x, g_scale[o  ], g_shift[o  ]), 0.f);
    v.y = fmaxf(fmaf(v.y, g_scale[o+1], g_shift[o+1]), 0.f);
    v.z = fmaxf(fmaf(v.z, g_scale[o+2], g_shift[o+2]), 0.f);
    v.w = fmaxf(fmaf(v.w, g_scale[o+3], g_shift[o+3]), 0.f);
    *(float4*)(out + i) = v;
}

// ---------------- launch -----------------------------------------------------
extern "C" void kernel_launch(void* const* d_in, const int* in_sizes, int n_in,
                              void* d_out, int out_size) {
    const float* x     = (const float*)d_in[0];
    const float* ew    = (const float*)d_in[1];
    const float* w     = (const float*)d_in[2];
    const float* bias  = (const float*)d_in[3]; (void)bias; // cancels under BN
    const float* gamma = (const float*)d_in[4];
    const float* beta  = (const float*)d_in[5];
    const int*   esrc  = (const int*)d_in[6];
    const int*   edst  = (const int*)d_in[7];
    float* out = (float*)d_out;
    (void)in_sizes; (void)n_in; (void)out_size;

    // CSR build (by dst)
    k_zero<<<(V_+255)/256, 256>>>();
    k_hist<<<E_/256, 256>>>(edst);
    k_scan<<<1, 1024>>>();
    k_scatter<<<E_/256, 256>>>(esrc, edst, ew);

    // Chebyshev recursion (gather SpMM, no atomics)
    k_spmm<<<V_*2, 256>>>(x, 1);
    k_spmm<<<V_*2, 256>>>(x, 2);
    k_spmm<<<V_*2, 256>>>(x, 3);

    // TF32 GEMM -> raw output
    dim3 gg(V_/BM, FOUT_/BN, B_);
    k_gemm<<<gg, 256>>>(x, w, out);

    // BatchNorm + ReLU
    k_bnstats<<<1024, 256>>>(out);
    k_bnfinal<<<1, FOUT_>>>(gamma, beta);
    k_bnapply<<<(ROWS_*FOUT_)/4/256, 256>>>(out);
}

// round 3
// speedup vs baseline: 1.1589x; 1.1589x over previous
#include <cuda_runtime.h>
#include <cstdint>

// Problem constants (fixed by the dataset)
#define B_    8
#define V_    12288
#define E_    98304
#define FIN_  256
#define FOUT_ 256
#define KCH_  4
#define BF_   (B_*FIN_)    // 2048 floats per node row (node-major layout)
#define ROWS_ (B_*V_)      // 98304 output rows

// ---------------- scratch (device globals: no runtime allocation) ----------
__device__ float g_T1[(size_t)V_*BF_];   // T1 = L x          [V][B*Fin]
__device__ float g_T2[(size_t)V_*BF_];   // T2 = 2 L T1 - x
__device__ float g_T3[(size_t)V_*BF_];   // T3 = 2 L T2 - T1
__device__ int   g_rowptr[V_+1];
__device__ int   g_cursor[V_];
__device__ int   g_cnt[V_];
__device__ int   g_col[E_];              // src indices sorted by dst
__device__ float g_w[E_];                // weights sorted by dst
__device__ float g_sum[FOUT_], g_sq[FOUT_];
__device__ float g_scale[FOUT_], g_shift[FOUT_];

// ---------------- CSR build -------------------------------------------------
__global__ void k_zero() {
    int i = blockIdx.x*blockDim.x + threadIdx.x;
    if (i < V_) g_cnt[i] = 0;
    if (i < FOUT_) { g_sum[i] = 0.f; g_sq[i] = 0.f; }
}

__global__ void k_hist(const int* __restrict__ dst) {
    int e = blockIdx.x*blockDim.x + threadIdx.x;
    if (e < E_) atomicAdd(&g_cnt[dst[e]], 1);
}

// exclusive scan over V_=12288 counts; 1 block of 1024 threads, 12 counts each
__global__ void k_scan() {
    __shared__ int sh[1024];
    int t = threadIdx.x;
    int base = t*12;
    int loc[12];
    int s = 0;
    #pragma unroll
    for (int i = 0; i < 12; ++i) { loc[i] = s; s += g_cnt[base+i]; }
    sh[t] = s;
    __syncthreads();
    for (int off = 1; off < 1024; off <<= 1) {
        int v = 0;
        if (t >= off) v = sh[t-off];
        __syncthreads();
        if (t >= off) sh[t] += v;
        __syncthreads();
    }
    int pre = (t == 0) ? 0 : sh[t-1];
    #pragma unroll
    for (int i = 0; i < 12; ++i) {
        int p = pre + loc[i];
        g_rowptr[base+i] = p;
        g_cursor[base+i] = p;
    }
    if (t == 1023) g_rowptr[V_] = sh[1023];
}

__global__ void k_scatter(const int* __restrict__ src, const int* __restrict__ dst,
                          const float* __restrict__ ew) {
    int e = blockIdx.x*blockDim.x + threadIdx.x;
    if (e < E_) {
        int d = dst[e];
        int p = atomicAdd(&g_cursor[d], 1);
        g_col[p] = src[e];
        g_w[p]   = ew[e];
    }
}

// ---------------- SpMM: Chebyshev recursion --------------------------------
// one block per node; 256 threads cover all 2048 floats (2 float4 each);
// 2-edge manual unroll -> 4 independent gathers in flight per thread.
__device__ __forceinline__ void fma4(float4& acc, float wt, const float4& t) {
    acc.x = fmaf(wt, t.x, acc.x);
    acc.y = fmaf(wt, t.y, acc.y);
    acc.z = fmaf(wt, t.z, acc.z);
    acc.w = fmaf(wt, t.w, acc.w);
}

__global__ __launch_bounds__(256) void k_spmm(const float* __restrict__ x, int stage) {
    const float* y;  const float* p2 = nullptr;  float* o;
    long ys, ps = 0;
    const int v  = blockIdx.x;
    const int j0 = threadIdx.x*4;
    const int j1 = j0 + 1024;
    const long xo0 = (long)(j0>>8)*((long)V_*FIN_) + (j0&255);
    const long xo1 = (long)(j1>>8)*((long)V_*FIN_) + (j1&255);
    long yo0, yo1, po0 = 0, po1 = 0;
    if (stage == 1)      { y = x;    ys = FIN_; yo0 = xo0; yo1 = xo1; o = g_T1; }
    else if (stage == 2) { y = g_T1; ys = BF_;  yo0 = j0;  yo1 = j1;
                           p2 = x;   ps = FIN_; po0 = xo0; po1 = xo1; o = g_T2; }
    else                 { y = g_T2; ys = BF_;  yo0 = j0;  yo1 = j1;
                           p2 = g_T1; ps = BF_; po0 = j0;  po1 = j1;  o = g_T3; }

    int r0 = g_rowptr[v], r1 = g_rowptr[v+1];
    float4 a0 = make_float4(0,0,0,0), a1 = make_float4(0,0,0,0);

    int e = r0;
    #pragma unroll 1
    for (; e + 2 <= r1; e += 2) {
        int   s0 = __ldg(&g_col[e]),   s1 = __ldg(&g_col[e+1]);
        float w0 = __ldg(&g_w[e]),     w1 = __ldg(&g_w[e+1]);
        float4 t00 = *(const float4*)(y + yo0 + (long)s0*ys);
        float4 t01 = *(const float4*)(y + yo1 + (long)s0*ys);
        float4 t10 = *(const float4*)(y + yo0 + (long)s1*ys);
        float4 t11 = *(const float4*)(y + yo1 + (long)s1*ys);
        fma4(a0, w0, t00); fma4(a1, w0, t01);
        fma4(a0, w1, t10); fma4(a1, w1, t11);
    }
    if (e < r1) {
        int   s0 = __ldg(&g_col[e]);
        float w0 = __ldg(&g_w[e]);
        float4 t00 = *(const float4*)(y + yo0 + (long)s0*ys);
        float4 t01 = *(const float4*)(y + yo1 + (long)s0*ys);
        fma4(a0, w0, t00); fma4(a1, w0, t01);
    }
    if (p2) {
        float4 t0 = *(const float4*)(p2 + po0 + (long)v*ps);
        float4 t1 = *(const float4*)(p2 + po1 + (long)v*ps);
        a0.x = 2.f*a0.x - t0.x; a0.y = 2.f*a0.y - t0.y;
        a0.z = 2.f*a0.z - t0.z; a0.w = 2.f*a0.w - t0.w;
        a1.x = 2.f*a1.x - t1.x; a1.y = 2.f*a1.y - t1.y;
        a1.z = 2.f*a1.z - t1.z; a1.w = 2.f*a1.w - t1.w;
    }
    *(float4*)(o + (long)v*BF_ + j0) = a0;
    *(float4*)(o + (long)v*BF_ + j1) = a1;
}

// ---------------- TF32 tensor-core GEMM (double-buffered, fused BN stats) ---
// out[b,v,o] = sum_p sum_i A_p(v,b,i) * W[p,i,o]
// A_0 = x (layout [B][V][Fin]); A_1..3 = g_T1..3 (layout [V][B*Fin])
// Bias omitted: constant per-channel shift cancels through BN mean subtraction.
#define BM 128
#define BN 128
#define BK 16
#define NTILES (KCH_ * FIN_ / BK)   // 64

__device__ __forceinline__ uint32_t f2tf(float f) {
    uint32_t u;
    asm("cvt.rna.tf32.f32 %0, %1;" : "=r"(u) : "f"(f));
    return u;
}

__global__ __launch_bounds__(256) void k_gemm(const float* __restrict__ x,
                                              const float* __restrict__ w,
                                              float* __restrict__ out) {
    __shared__ uint32_t As[2][BK][BM+4];
    __shared__ uint32_t Bs[2][BK][BN+4];
    __shared__ float s_s[BN], s_q[BN];

    const int b      = blockIdx.z;
    const int nbase0 = blockIdx.x * BN;   // N split in x -> neighbors share A tile (L2)
    const int vbase  = blockIdx.y * BM;
    const int tid  = threadIdx.x;
    const int lane = tid & 31, warp = tid >> 5;
    const int wm = warp & 3, wn = warp >> 2;
    const int g = lane >> 2, tg = lane & 3;
    const int a_c = tid & 3,  a_m  = tid >> 2;   // A: k-quad, row (and row+64)
    const int b_n4 = tid & 31, b_k = tid >> 5;   // B: float4 col, k row (and +8)

    if (tid < BN) { s_s[tid] = 0.f; s_q[tid] = 0.f; }

    float acc[2][8][4];
    #pragma unroll
    for (int i = 0; i < 2; ++i)
        #pragma unroll
        for (int j = 0; j < 8; ++j)
            #pragma unroll
            for (int c = 0; c < 4; ++c) acc[i][j][c] = 0.f;

    float4 ra[2], rb[2];

    // tile prefetch (global -> regs)
    auto prefetch = [&](int t) {
        int p  = t >> 4;
        int kb = (t & 15) * BK;
        const float* abase; long astride;
        if (p == 0)      { abase = x    + (long)b*V_*FIN_; astride = FIN_; }
        else if (p == 1) { abase = g_T1 + (long)b*FIN_;    astride = BF_;  }
        else if (p == 2) { abase = g_T2 + (long)b*FIN_;    astride = BF_;  }
        else             { abase = g_T3 + (long)b*FIN_;    astride = BF_;  }
        const float* wp = w + (long)p*FIN_*FOUT_ + nbase0;
        ra[0] = *(const float4*)(abase + (long)(vbase + a_m     )*astride + kb + a_c*4);
        ra[1] = *(const float4*)(abase + (long)(vbase + a_m + 64)*astride + kb + a_c*4);
        rb[0] = *(const float4*)(wp + (long)(kb + b_k    )*FOUT_ + b_n4*4);
        rb[1] = *(const float4*)(wp + (long)(kb + b_k + 8)*FOUT_ + b_n4*4);
    };

    prefetch(0);
    int cur = 0;
    #pragma unroll 1
    for (int t = 0; t < NTILES; ++t) {
        // store regs -> smem[cur] (convert to tf32 here, off the load path)
        As[cur][a_c*4+0][a_m] = f2tf(ra[0].x);
        As[cur][a_c*4+1][a_m] = f2tf(ra[0].y);
        As[cur][a_c*4+2][a_m] = f2tf(ra[0].z);
        As[cur][a_c*4+3][a_m] = f2tf(ra[0].w);
        As[cur][a_c*4+0][a_m+64] = f2tf(ra[1].x);
        As[cur][a_c*4+1][a_m+64] = f2tf(ra[1].y);
        As[cur][a_c*4+2][a_m+64] = f2tf(ra[1].z);
        As[cur][a_c*4+3][a_m+64] = f2tf(ra[1].w);
        {
            uint32_t* d0 = &Bs[cur][b_k    ][b_n4*4];
            uint32_t* d1 = &Bs[cur][b_k + 8][b_n4*4];
            d0[0] = f2tf(rb[0].x); d0[1] = f2tf(rb[0].y);
            d0[2] = f2tf(rb[0].z); d0[3] = f2tf(rb[0].w);
            d1[0] = f2tf(rb[1].x); d1[1] = f2tf(rb[1].y);
            d1[2] = f2tf(rb[1].z); d1[3] = f2tf(rb[1].w);
        }
        __syncthreads();
        if (t + 1 < NTILES) prefetch(t + 1);   // overlap global loads with mma

        #pragma unroll
        for (int kk = 0; kk < BK; kk += 8) {
            uint32_t a[2][4];
            #pragma unroll
            for (int mt = 0; mt < 2; ++mt) {
                int mb = wm*32 + mt*16;
                a[mt][0] = As[cur][kk+tg  ][mb+g  ];
                a[mt][1] = As[cur][kk+tg  ][mb+g+8];
                a[mt][2] = As[cur][kk+tg+4][mb+g  ];
                a[mt][3] = As[cur][kk+tg+4][mb+g+8];
            }
            #pragma unroll
            for (int nt = 0; nt < 8; ++nt) {
                int nb = wn*64 + nt*8;
                uint32_t b0 = Bs[cur][kk+tg  ][nb+g];
                uint32_t b1 = Bs[cur][kk+tg+4][nb+g];
                #pragma unroll
                for (int mt = 0; mt < 2; ++mt) {
                    asm volatile(
                        "mma.sync.aligned.m16n8k8.row.col.f32.tf32.tf32.f32 "
                        "{%0,%1,%2,%3}, {%4,%5,%6,%7}, {%8,%9}, {%0,%1,%2,%3};\n"
                        : "+f"(acc[mt][nt][0]), "+f"(acc[mt][nt][1]),
                          "+f"(acc[mt][nt][2]), "+f"(acc[mt][nt][3])
                        : "r"(a[mt][0]), "r"(a[mt][1]),
                          "r"(a[mt][2]), "r"(a[mt][3]),
                          "r"(b0), "r"(b1));
                }
            }
        }
        cur ^= 1;
    }

    // epilogue: write raw (pre-BN) result
    #pragma unroll
    for (int mt = 0; mt < 2; ++mt) {
        int row0 = vbase + wm*32 + mt*16 + g;
        #pragma unroll
        for (int nt = 0; nt < 8; ++nt) {
            int col = nbase0 + wn*64 + nt*8 + tg*2;
            float2* p0 = (float2*)&out[((long)b*V_ + row0    )*FOUT_ + col];
            float2* p1 = (float2*)&out[((long)b*V_ + row0 + 8)*FOUT_ + col];
            *p0 = make_float2(acc[mt][nt][0], acc[mt][nt][1]);
            *p1 = make_float2(acc[mt][nt][2], acc[mt][nt][3]);
        }
    }

    // fused BN stats: per-column sum / sumsq over this block's 128 rows
    #pragma unroll
    for (int nt = 0; nt < 8; ++nt) {
        float s0 = acc[0][nt][0] + acc[0][nt][2] + acc[1][nt][0] + acc[1][nt][2];
        float s1 = acc[0][nt][1] + acc[0][nt][3] + acc[1][nt][1] + acc[1][nt][3];
        float q0 = acc[0][nt][0]*acc[0][nt][0] + acc[0][nt][2]*acc[0][nt][2]
                 + acc[1][nt][0]*acc[1][nt][0] + acc[1][nt][2]*acc[1][nt][2];
        float q1 = acc[0][nt][1]*acc[0][nt][1] + acc[0][nt][3]*acc[0][nt][3]
                 + acc[1][nt][1]*acc[1][nt][1] + acc[1][nt][3]*acc[1][nt][3];
        #pragma unroll
        for (int m = 4; m <= 16; m <<= 1) {
            s0 += __shfl_xor_sync(0xffffffffu, s0, m);
            s1 += __shfl_xor_sync(0xffffffffu, s1, m);
            q0 += __shfl_xor_sync(0xffffffffu, q0, m);
            q1 += __shfl_xor_sync(0xffffffffu, q1, m);
        }
        if (lane < 4) {
            int colr = wn*64 + nt*8 + tg*2;
            atomicAdd(&s_s[colr  ], s0); atomicAdd(&s_q[colr  ], q0);
            atomicAdd(&s_s[colr+1], s1); atomicAdd(&s_q[colr+1], q1);
        }
    }
    __syncthreads();
    if (tid < BN) {
        atomicAdd(&g_sum[nbase0 + tid], s_s[tid]);
        atomicAdd(&g_sq[nbase0 + tid],  s_q[tid]);
    }
}

// ---------------- BatchNorm finalize + apply + ReLU -------------------------
__global__ void k_bnfinal(const float* __restrict__ gamma,
                          const float* __restrict__ beta) {
    int o = threadIdx.x;
    const float n = (float)ROWS_;
    float mean = g_sum[o] / n;
    float var  = g_sq[o] / n - mean*mean;      // biased variance (torch-style)
    float sc   = gamma[o] * rsqrtf(var + 1e-5f);
    g_scale[o] = sc;
    g_shift[o] = beta[o] - mean*sc;
}

__global__ __launch_bounds__(256) void k_bnapply(float* __restrict__ out) {
    long i = ((long)blockIdx.x*blockDim.x + threadIdx.x) * 4;
    float4 v = *(float4*)(out + i);
    int o = (int)(i & 255);
    v.x = fmaxf(fmaf(v.x, g_scale[o  ], g_shift[o  ]), 0.f);
    v.y = fmaxf(fmaf(v.y, g_scale[o+1], g_shift[o+1]), 0.f);
    v.z = fmaxf(fmaf(v.z, g_scale[o+2], g_shift[o+2]), 0.f);
    v.w = fmaxf(fmaf(v.w, g_scale[o+3], g_shift[o+3]), 0.f);
    *(float4*)(out + i) = v;
}

// ---------------- launch -----------------------------------------------------
extern "C" void kernel_launch(void* const* d_in, const int* in_sizes, int n_in,
                              void* d_out, int out_size) {
    const float* x     = (const float*)d_in[0];
    const float* ew    = (const float*)d_in[1];
    const float* w     = (const float*)d_in[2];
    const float* bias  = (const float*)d_in[3]; (void)bias; // cancels under BN
    const float* gamma = (const float*)d_in[4];
    const float* beta  = (const float*)d_in[5];
    const int*   esrc  = (const int*)d_in[6];
    const int*   edst  = (const int*)d_in[7];
    float* out = (float*)d_out;
    (void)in_sizes; (void)n_in; (void)out_size;

    // CSR build (by dst)
    k_zero<<<(V_+255)/256, 256>>>();
    k_hist<<<E_/256, 256>>>(edst);
    k_scan<<<1, 1024>>>();
    k_scatter<<<E_/256, 256>>>(esrc, edst, ew);

    // Chebyshev recursion (gather SpMM, no atomics)
    k_spmm<<<V_, 256>>>(x, 1);
    k_spmm<<<V_, 256>>>(x, 2);
    k_spmm<<<V_, 256>>>(x, 3);

    // TF32 GEMM -> raw output + fused BN statistics
    dim3 gg(FOUT_/BN, V_/BM, B_);   // N split in x: adjacent blocks share A tiles
    k_gemm<<<gg, 256>>>(x, w, out);

    // BatchNorm finalize + apply + ReLU
    k_bnfinal<<<1, FOUT_>>>(gamma, beta);
    k_bnapply<<<(ROWS_*FOUT_)/4/256, 256>>>(out);
}